// round 16
// baseline (speedup 1.0000x reference)
#include <cuda_runtime.h>
#include <cuda_bf16.h>

#define B_    8
#define N_    8192
#define CIN   128
#define COUT  256
#define M_    2048
#define KNN_K 16

typedef unsigned long long ull;

__device__ float g_h[(size_t)B_ * N_ * COUT];
__device__ float g_psum [256 * COUT];
__device__ float g_psum2[256 * COUT];
__device__ float g_mean[COUT];
__device__ float g_rstd[COUT];
__device__ int   g_nbr[(size_t)B_ * M_ * KNN_K];

__device__ __forceinline__ ull pk2(float lo, float hi) {
    ull r; asm("mov.b64 %0, {%1,%2};" : "=l"(r) : "f"(lo), "f"(hi)); return r;
}
__device__ __forceinline__ void upk2(ull v, float& lo, float& hi) {
    asm("mov.b64 {%0,%1}, %2;" : "=f"(lo), "=f"(hi) : "l"(v));
}
__device__ __forceinline__ ull add2(ull a, ull b) {
    ull r; asm("add.rn.f32x2 %0, %1, %2;" : "=l"(r) : "l"(a), "l"(b)); return r;
}
__device__ __forceinline__ ull mul2(ull a, ull b) {
    ull r; asm("mul.rn.f32x2 %0, %1, %2;" : "=l"(r) : "l"(a), "l"(b)); return r;
}
__device__ __forceinline__ ull fma2_(ull a, ull b, ull c) {
    ull r; asm("fma.rn.f32x2 %0, %1, %2, %3;" : "=l"(r) : "l"(a), "l"(b), "l"(c)); return r;
}
__device__ __forceinline__ unsigned smem_u32_of(const void* p) {
    unsigned a; asm("{ .reg .u64 t; cvta.to.shared.u64 t, %1; cvt.u32.u64 %0, t; }"
                    : "=r"(a) : "l"(p));
    return a;
}
__device__ __forceinline__ unsigned cluster_rank_() {
    unsigned r; asm("mov.u32 %0, %%cluster_ctarank;" : "=r"(r)); return r;
}
__device__ __forceinline__ unsigned mapa_sh(unsigned addr, unsigned rank) {
    unsigned r; asm("mapa.shared::cluster.u32 %0, %1, %2;" : "=r"(r) : "r"(addr), "r"(rank));
    return r;
}

#define NFPS  16                  // 2 CTAs per batch
#define HALF_ (N_/2)              // 4096 points per CTA
#define MM_PAD 132
#define SMEM_K1 (2 * 128 * MM_PAD * 4)   // 135168 B

// smem offsets for FPS part
#define OFF_SLOTSELF 0            // ull
#define OFF_SELFCOPY 8            // ull[2]
#define OFF_SLOTPEER 24           // ull[2]
#define OFF_COORDS   512

__global__ __launch_bounds__(1024, 1) __cluster_dims__(2, 1, 1)
void k1_fps_mm(
    const float* __restrict__ x, const float* __restrict__ p1,
    const float* __restrict__ W, float* __restrict__ out)
{
    extern __shared__ char smem[];
    const int tid = threadIdx.x;

    if (blockIdx.x < NFPS) {
        // ---------------- FPS: 2-CTA cluster per batch ----------------
        ull*   slotSelf = (ull*)(smem + OFF_SLOTSELF);
        ull*   selfCopy = (ull*)(smem + OFF_SELFCOPY);
        ull*   slotPeer = (ull*)(smem + OFF_SLOTPEER);
        float* sx = (float*)(smem + OFF_COORDS);
        float* sy = sx + N_;
        float* sz = sy + N_;
        const int b    = blockIdx.x >> 1;
        const unsigned rank = cluster_rank_();
        const unsigned smb  = smem_u32_of(smem);
        const float* pb = p1 + (size_t)b * N_ * 3;

        // full coord copy (both CTAs)
        for (int i = tid; i < N_; i += 1024) {
            sx[i] = pb[3*i]; sy[i] = pb[3*i+1]; sz[i] = pb[3*i+2];
        }
        if (tid == 0) {
            slotSelf[0] = 0; selfCopy[0] = 0; selfCopy[1] = 0;
            slotPeer[0] = 0; slotPeer[1] = 0;
        }
        __syncthreads();
        // peer smem must be initialized before first remote store
        asm volatile("barrier.cluster.arrive.aligned;" ::: "memory");
        asm volatile("barrier.cluster.wait.aligned;"   ::: "memory");

        // this CTA's 4 points per thread: idx = rank*4096 + k*1024 + tid
        const int base = (int)rank * HALF_;
        float lx[4], ly[4], lz[4], dist[4];
        #pragma unroll
        for (int k = 0; k < 4; k++) {
            int gi = base + k*1024 + tid;
            lx[k] = sx[gi]; ly[k] = sy[gi]; lz[k] = sz[gi];
            dist[k] = 1e10f;
        }
        ull X[2], Y[2], Z[2];
        #pragma unroll
        for (int j = 0; j < 2; j++) {
            X[j]=pk2(lx[j],lx[j+2]); Y[j]=pk2(ly[j],ly[j+2]); Z[j]=pk2(lz[j],lz[j+2]);
        }

        float* p2o = out + (size_t)B_*M_*COUT + (size_t)b*M_*3;
        int far = 0;
        if (rank == 0 && tid == 0) { p2o[0]=sx[0]; p2o[1]=sy[0]; p2o[2]=sz[0]; }

        const unsigned remoteAddrBase = mapa_sh(smb + OFF_SLOTPEER, rank ^ 1u);

        for (int step = 1; step < M_; step++) {
            const int p = step & 1;
            float cx = sx[far], cy = sy[far], cz = sz[far];
            ull ncx = pk2(-cx,-cx), ncy = pk2(-cy,-cy), ncz = pk2(-cz,-cz);
            #pragma unroll
            for (int j = 0; j < 2; j++) {
                ull dx = add2(X[j], ncx);
                ull dy = add2(Y[j], ncy);
                ull dz = add2(Z[j], ncz);
                ull d2 = add2(add2(mul2(dx,dx), mul2(dy,dy)), mul2(dz,dz));
                float dl, dh; upk2(d2, dl, dh);
                dist[j]   = fminf(dist[j],   dl);
                dist[j+2] = fminf(dist[j+2], dh);
            }
            float bd = -1.0f; int bk = 0;
            #pragma unroll
            for (int k = 0; k < 4; k++) if (dist[k] > bd) { bd = dist[k]; bk = k; }
            unsigned gidx  = (unsigned)(base + bk*1024 + tid);
            unsigned dbits = __float_as_uint(bd);
            unsigned mmax  = __reduce_max_sync(0xffffffffu, dbits);
            unsigned cidx  = (dbits == mmax) ? gidx : 0xffffffffu;
            unsigned mix   = __reduce_min_sync(0xffffffffu, cidx);
            if ((tid & 31) == 0)
                atomicMax(slotSelf, ((ull)step << 46) | ((ull)mmax << 14)
                                      | (ull)(16383u - mix));
            __syncthreads();
            if (tid == 0) {
                ull k = slotSelf[0];
                selfCopy[p] = k;
                asm volatile("st.shared::cluster.u64 [%0], %1;"
                             :: "r"(remoteAddrBase + (unsigned)p*8), "l"(k) : "memory");
            }
            asm volatile("barrier.cluster.arrive.aligned;" ::: "memory");
            asm volatile("barrier.cluster.wait.aligned;"   ::: "memory");
            ull a = selfCopy[p], bb2 = slotPeer[p];
            ull win = (a > bb2) ? a : bb2;
            far = 16383 - (int)(win & 0x3FFFu);
            if (rank == 0 && tid == 0) {
                p2o[3*step]=sx[far]; p2o[3*step+1]=sy[far]; p2o[3*step+2]=sz[far];
            }
        }
    } else {
        // ---------------- matmul: unchanged ----------------
        const int bid  = blockIdx.x - NFPS;
        const int row0 = (bid >> 1) * 128;
        const int col0 = (bid & 1) * 128;
        float* sA = (float*)smem;
        float* sB = sA + 128 * MM_PAD;

        #pragma unroll
        for (int c = 0; c < 4; c++) {
            int lin = c * 1024 + tid;
            int rr = lin >> 5, kq = lin & 31;
            float4 va = *(const float4*)(x + (size_t)(row0+rr)*CIN + kq*4);
            sA[(kq*4+0)*MM_PAD+rr]=va.x; sA[(kq*4+1)*MM_PAD+rr]=va.y;
            sA[(kq*4+2)*MM_PAD+rr]=va.z; sA[(kq*4+3)*MM_PAD+rr]=va.w;
            float4 vb = *(const float4*)(W + (size_t)(col0+rr)*CIN + kq*4);
            sB[(kq*4+0)*MM_PAD+rr]=vb.x; sB[(kq*4+1)*MM_PAD+rr]=vb.y;
            sB[(kq*4+2)*MM_PAD+rr]=vb.z; sB[(kq*4+3)*MM_PAD+rr]=vb.w;
        }
        __syncthreads();

        const int tm = tid >> 5, tn = tid & 31;
        ull acc[4][2];
        #pragma unroll
        for (int i = 0; i < 4; i++) { acc[i][0]=0ull; acc[i][1]=0ull; }

        #pragma unroll 4
        for (int k = 0; k < CIN; k++) {
            float4 av = *(const float4*)&sA[k*MM_PAD + tm*4];
            float4 bv = *(const float4*)&sB[k*MM_PAD + tn*4];
            ull b01 = pk2(bv.x, bv.y), b23 = pk2(bv.z, bv.w);
            ull a0 = pk2(av.x, av.x);
            acc[0][0]=fma2_(a0,b01,acc[0][0]); acc[0][1]=fma2_(a0,b23,acc[0][1]);
            ull a1 = pk2(av.y, av.y);
            acc[1][0]=fma2_(a1,b01,acc[1][0]); acc[1][1]=fma2_(a1,b23,acc[1][1]);
            ull a2 = pk2(av.z, av.z);
            acc[2][0]=fma2_(a2,b01,acc[2][0]); acc[2][1]=fma2_(a2,b23,acc[2][1]);
            ull a3 = pk2(av.w, av.w);
            acc[3][0]=fma2_(a3,b01,acc[3][0]); acc[3][1]=fma2_(a3,b23,acc[3][1]);
        }

        #pragma unroll
        for (int i = 0; i < 4; i++) {
            float r0,r1,r2,r3;
            upk2(acc[i][0], r0, r1); upk2(acc[i][1], r2, r3);
            *(float4*)(g_h + (size_t)(row0 + tm*4 + i)*COUT + col0 + tn*4)
                = make_float4(r0, r1, r2, r3);
        }
    }
}

// ---------------- K2 / K3: BN stats (unchanged) ----------------
__global__ void k2_stats()
{
    const int rb = blockIdx.x, c = threadIdx.x;
    const float* hp = g_h + (size_t)rb * 256 * COUT + c;
    float s = 0.f, s2 = 0.f;
    #pragma unroll 8
    for (int r = 0; r < 256; r++) {
        float v = hp[(size_t)r * COUT];
        s  = __fadd_rn(s, v);
        s2 = __fmaf_rn(v, v, s2);
    }
    g_psum [rb*COUT + c] = s;
    g_psum2[rb*COUT + c] = s2;
}

__global__ void k3_finalize()
{
    const int c = threadIdx.x;
    float s = 0.f, s2 = 0.f;
    #pragma unroll 8
    for (int rb = 0; rb < 256; rb++) {
        s  += g_psum [rb*COUT + c];
        s2 += g_psum2[rb*COUT + c];
    }
    const float inv = 1.0f / 65536.0f;
    float mean = s * inv;
    float var  = __fmaf_rn(-mean, mean, s2 * inv);
    g_mean[c] = mean;
    g_rstd[c] = __fdiv_rn(1.0f, __fsqrt_rn(__fadd_rn(var, 1e-5f)));
}

// ---------------- K4: kNN (unchanged, passing numerics) ----------------
#define K4_SMEM (4*N_*4 + 8*512*8)
__global__ __launch_bounds__(256, 1) void k4_knn(
    const float* __restrict__ p1, const float* __restrict__ out)
{
    extern __shared__ char smraw[];
    float* sx  = (float*)smraw;
    float* sy  = sx + N_;
    float* sz  = sy + N_;
    float* srr = sz + N_;
    ull*  cand = (ull*)(srr + N_);

    const int b   = blockIdx.x >> 4;
    const int blk = blockIdx.x & 15;
    const float* pb = p1 + (size_t)b * N_ * 3;

    for (int i = threadIdx.x; i < N_; i += 256) {
        float a = pb[3*i], bb = pb[3*i+1], c = pb[3*i+2];
        sx[i]=a; sy[i]=bb; sz[i]=c;
        srr[i] = __fmaf_rn(c, c, __fmaf_rn(a, a, __fmul_rn(bb, bb)));
    }
    __syncthreads();

    const int w = threadIdx.x >> 5, lane = threadIdx.x & 31;
    const float* p2base = out + (size_t)B_*M_*COUT;

    for (int qi = 0; qi < 16; qi++) {
        const int m = blk*128 + qi*8 + w;
        const float* q = p2base + ((size_t)b*M_ + m)*3;
        const float qx = q[0], qy = q[1], qz = q[2];
        const float qq = __fmaf_rn(qz, qz, __fmaf_rn(qx, qx, __fmul_rn(qy, qy)));

        float kd[16]; int ki[16];
        #pragma unroll
        for (int j = 0; j < 16; j++) { kd[j] = 3.4e38f; ki[j] = 0x7fffffff; }

        for (int i = lane; i < N_; i += 32) {
            float dot = __fmaf_rn(qz, sz[i], __fmaf_rn(qy, sy[i], __fmul_rn(qx, sx[i])));
            float d2  = __fmaf_rn(-2.0f, dot, __fadd_rn(qq, srr[i]));
            if (d2 < kd[15]) {
                float cd = d2; int ci = i;
                #pragma unroll
                for (int j = 0; j < 16; j++) {
                    if (cd < kd[j]) {
                        float td = kd[j]; int ti = ki[j];
                        kd[j] = cd; ki[j] = ci; cd = td; ci = ti;
                    }
                }
            }
        }
        ull* my = cand + w*512 + lane*16;
        #pragma unroll
        for (int j = 0; j < 16; j++) {
            unsigned ub = __float_as_uint(kd[j]);
            ub = (ub & 0x80000000u) ? ~ub : (ub | 0x80000000u);
            my[j] = ((ull)ub << 32) | (unsigned)ki[j];
        }
        __syncwarp();

        int ptr = 0;
        int* nbrq = g_nbr + ((size_t)b*M_ + m) * KNN_K;
        for (int r = 0; r < KNN_K; r++) {
            ull mykey = cand[w*512 + lane*16 + ptr];
            ull best = mykey; int bl = lane;
            #pragma unroll
            for (int o = 16; o > 0; o >>= 1) {
                ull ok = __shfl_down_sync(0xffffffffu, best, o);
                int ol = __shfl_down_sync(0xffffffffu, bl, o);
                if (ok < best) { best = ok; bl = ol; }
            }
            best = __shfl_sync(0xffffffffu, best, 0);
            bl   = __shfl_sync(0xffffffffu, bl, 0);
            if (lane == bl) ptr++;
            if (lane == 0) nbrq[r] = (int)(best & 0xffffffffu);
        }
        __syncwarp();
    }
}

// ---------------- K5: gather + max-pool + BN + ReLU (unchanged) ----------------
__global__ __launch_bounds__(256) void k5_out(
    const float* __restrict__ gamma, const float* __restrict__ beta,
    float* __restrict__ out)
{
    __shared__ int snbr[KNN_K];
    const int bid = blockIdx.x;
    const int b = bid >> 11, m = bid & 2047;
    const int c = threadIdx.x;
    if (c < KNN_K) snbr[c] = g_nbr[((size_t)b*M_ + m)*KNN_K + c];
    __syncthreads();

    float mx = -3.4e38f, mn = 3.4e38f;
    #pragma unroll
    for (int i = 0; i < KNN_K; i++) {
        float v = g_h[((size_t)b*N_ + snbr[i])*COUT + c];
        mx = fmaxf(mx, v); mn = fminf(mn, v);
    }
    float g = gamma[c];
    float h = (g >= 0.0f) ? mx : mn;
    float t = __fmul_rn(__fmul_rn(__fadd_rn(h, -g_mean[c]), g_rstd[c]), g);
    t = __fadd_rn(t, beta[c]);
    out[((size_t)b*M_ + m)*COUT + c] = fmaxf(t, 0.0f);
}

// ---------------- launch ----------------
extern "C" void kernel_launch(void* const* d_in, const int* in_sizes, int n_in,
                              void* d_out, int out_size)
{
    (void)in_sizes; (void)n_in; (void)out_size;
    const float* x     = (const float*)d_in[0];
    const float* p1    = (const float*)d_in[1];
    const float* W     = (const float*)d_in[2];
    const float* gamma = (const float*)d_in[3];
    const float* beta  = (const float*)d_in[4];
    float* out = (float*)d_out;

    cudaFuncSetAttribute(k1_fps_mm, cudaFuncAttributeMaxDynamicSharedMemorySize, SMEM_K1);
    cudaFuncSetAttribute(k4_knn,    cudaFuncAttributeMaxDynamicSharedMemorySize, K4_SMEM);

    k1_fps_mm<<<NFPS + (B_*N_/128)*(COUT/128), 1024, SMEM_K1>>>(x, p1, W, out);
    k2_stats<<<256, 256>>>();
    k3_finalize<<<1, 256>>>();
    k4_knn<<<B_ * 16, 256, K4_SMEM>>>(p1, out);
    k5_out<<<B_ * M_, 256>>>(gamma, beta, out);
}

// round 17
// speedup vs baseline: 1.2020x; 1.2020x over previous
#include <cuda_runtime.h>
#include <cuda_bf16.h>

#define B_    8
#define N_    8192
#define CIN   128
#define COUT  256
#define M_    2048
#define KNN_K 16

typedef unsigned long long ull;

__device__ float g_h[(size_t)B_ * N_ * COUT];
__device__ float g_psum [256 * COUT];
__device__ float g_psum2[256 * COUT];
__device__ float g_mean[COUT];
__device__ float g_rstd[COUT];
__device__ int   g_nbr[(size_t)B_ * M_ * KNN_K];

__device__ __forceinline__ ull pk2(float lo, float hi) {
    ull r; asm("mov.b64 %0, {%1,%2};" : "=l"(r) : "f"(lo), "f"(hi)); return r;
}
__device__ __forceinline__ void upk2(ull v, float& lo, float& hi) {
    asm("mov.b64 {%0,%1}, %2;" : "=f"(lo), "=f"(hi) : "l"(v));
}
__device__ __forceinline__ ull add2(ull a, ull b) {
    ull r; asm("add.rn.f32x2 %0, %1, %2;" : "=l"(r) : "l"(a), "l"(b)); return r;
}
__device__ __forceinline__ ull mul2(ull a, ull b) {
    ull r; asm("mul.rn.f32x2 %0, %1, %2;" : "=l"(r) : "l"(a), "l"(b)); return r;
}
__device__ __forceinline__ ull fma2_(ull a, ull b, ull c) {
    ull r; asm("fma.rn.f32x2 %0, %1, %2, %3;" : "=l"(r) : "l"(a), "l"(b), "l"(c)); return r;
}

// ---------------- K1: FPS (blocks 0..7) + matmul (blocks 8..1031) ----------------
#define MM_PAD 132
#define SMEM_K1 (2 * 128 * MM_PAD * 4)   // 135168 B (FPS needs ~98.4 KB)

__global__ __launch_bounds__(1024, 1) void k1_fps_mm(
    const float* __restrict__ x, const float* __restrict__ p1,
    const float* __restrict__ W, float* __restrict__ out)
{
    extern __shared__ char smem[];
    const int tid = threadIdx.x;

    if (blockIdx.x < B_) {
        // ---------------- FPS: one CTA per batch, streamlined reduction ----------
        ull*   slot = (ull*)smem;                // [2] parity double-buffer
        float* sx   = (float*)(smem + 512);
        float* sy   = sx + N_;
        float* sz   = sy + N_;
        const int b = blockIdx.x;
        const float* pb = p1 + (size_t)b * N_ * 3;

        float lx[8], ly[8], lz[8], dist[8];
        #pragma unroll
        for (int k = 0; k < 8; k++) {
            int gi = k * 1024 + tid;
            float a = pb[3*gi], bb = pb[3*gi+1], c = pb[3*gi+2];
            lx[k]=a; ly[k]=bb; lz[k]=c; sx[gi]=a; sy[gi]=bb; sz[gi]=c;
            dist[k] = 1e10f;
        }
        ull X[4], Y[4], Z[4];
        #pragma unroll
        for (int j = 0; j < 4; j++) {
            X[j]=pk2(lx[j],lx[j+4]); Y[j]=pk2(ly[j],ly[j+4]); Z[j]=pk2(lz[j],lz[j+4]);
        }
        if (tid == 0) { slot[0] = 0; slot[1] = 0; }
        __syncthreads();

        float* p2o = out + (size_t)B_*M_*COUT + (size_t)b*M_*3;
        int far = 0;
        if (tid == 0) { p2o[0]=sx[0]; p2o[1]=sy[0]; p2o[2]=sz[0]; }
        const int lane = tid & 31;

        for (int step = 1; step < M_; step++) {
            const int p = step & 1;
            float cx = sx[far], cy = sy[far], cz = sz[far];
            ull ncx = pk2(-cx,-cx), ncy = pk2(-cy,-cy), ncz = pk2(-cz,-cz);
            #pragma unroll
            for (int j = 0; j < 4; j++) {
                ull dx = add2(X[j], ncx);
                ull dy = add2(Y[j], ncy);
                ull dz = add2(Z[j], ncz);
                ull d2 = add2(add2(mul2(dx,dx), mul2(dy,dy)), mul2(dz,dz));
                float dl, dh; upk2(d2, dl, dh);
                dist[j]   = fminf(dist[j],   dl);
                dist[j+4] = fminf(dist[j+4], dh);
            }
            // thread-local argmax (strict > keeps earliest k => lowest gidx)
            float bd = -1.0f; int bk = 0;
            #pragma unroll
            for (int k = 0; k < 8; k++) if (dist[k] > bd) { bd = dist[k]; bk = k; }
            unsigned gidx  = (unsigned)(bk * 1024 + tid);
            unsigned dbits = __float_as_uint(bd);          // dist >= 0: bits monotone
            // warp reduction: max dist, then min index among maxima
            unsigned mmax = __reduce_max_sync(0xffffffffu, dbits);
            unsigned cidx = (dbits == mmax) ? gidx : 0xffffffffu;
            unsigned mix  = __reduce_min_sync(0xffffffffu, cidx);
            // cross-warp: monotonic step-prefixed key, no resets needed
            if (lane == 0)
                atomicMax(&slot[p], ((ull)step << 46) | ((ull)mmax << 14)
                                       | (ull)(16383u - mix));
            __syncthreads();    // drains smem atomics; single barrier per step
            ull win = slot[p];
            far = 16383 - (int)(win & 0x3FFFu);
            if (tid == 0) {
                p2o[3*step]=sx[far]; p2o[3*step+1]=sy[far]; p2o[3*step+2]=sz[far];
            }
        }
    } else {
        // ---------------- matmul: unchanged ----------------
        const int bid  = blockIdx.x - B_;
        const int row0 = (bid >> 1) * 128;
        const int col0 = (bid & 1) * 128;
        float* sA = (float*)smem;
        float* sB = sA + 128 * MM_PAD;

        #pragma unroll
        for (int c = 0; c < 4; c++) {
            int lin = c * 1024 + tid;
            int rr = lin >> 5, kq = lin & 31;
            float4 va = *(const float4*)(x + (size_t)(row0+rr)*CIN + kq*4);
            sA[(kq*4+0)*MM_PAD+rr]=va.x; sA[(kq*4+1)*MM_PAD+rr]=va.y;
            sA[(kq*4+2)*MM_PAD+rr]=va.z; sA[(kq*4+3)*MM_PAD+rr]=va.w;
            float4 vb = *(const float4*)(W + (size_t)(col0+rr)*CIN + kq*4);
            sB[(kq*4+0)*MM_PAD+rr]=vb.x; sB[(kq*4+1)*MM_PAD+rr]=vb.y;
            sB[(kq*4+2)*MM_PAD+rr]=vb.z; sB[(kq*4+3)*MM_PAD+rr]=vb.w;
        }
        __syncthreads();

        const int tm = tid >> 5, tn = tid & 31;
        ull acc[4][2];
        #pragma unroll
        for (int i = 0; i < 4; i++) { acc[i][0]=0ull; acc[i][1]=0ull; }

        #pragma unroll 4
        for (int k = 0; k < CIN; k++) {
            float4 av = *(const float4*)&sA[k*MM_PAD + tm*4];
            float4 bv = *(const float4*)&sB[k*MM_PAD + tn*4];
            ull b01 = pk2(bv.x, bv.y), b23 = pk2(bv.z, bv.w);
            ull a0 = pk2(av.x, av.x);
            acc[0][0]=fma2_(a0,b01,acc[0][0]); acc[0][1]=fma2_(a0,b23,acc[0][1]);
            ull a1 = pk2(av.y, av.y);
            acc[1][0]=fma2_(a1,b01,acc[1][0]); acc[1][1]=fma2_(a1,b23,acc[1][1]);
            ull a2 = pk2(av.z, av.z);
            acc[2][0]=fma2_(a2,b01,acc[2][0]); acc[2][1]=fma2_(a2,b23,acc[2][1]);
            ull a3 = pk2(av.w, av.w);
            acc[3][0]=fma2_(a3,b01,acc[3][0]); acc[3][1]=fma2_(a3,b23,acc[3][1]);
        }

        #pragma unroll
        for (int i = 0; i < 4; i++) {
            float r0,r1,r2,r3;
            upk2(acc[i][0], r0, r1); upk2(acc[i][1], r2, r3);
            *(float4*)(g_h + (size_t)(row0 + tm*4 + i)*COUT + col0 + tn*4)
                = make_float4(r0, r1, r2, r3);
        }
    }
}

// ---------------- K2 / K3: BN stats (unchanged) ----------------
__global__ void k2_stats()
{
    const int rb = blockIdx.x, c = threadIdx.x;
    const float* hp = g_h + (size_t)rb * 256 * COUT + c;
    float s = 0.f, s2 = 0.f;
    #pragma unroll 8
    for (int r = 0; r < 256; r++) {
        float v = hp[(size_t)r * COUT];
        s  = __fadd_rn(s, v);
        s2 = __fmaf_rn(v, v, s2);
    }
    g_psum [rb*COUT + c] = s;
    g_psum2[rb*COUT + c] = s2;
}

__global__ void k3_finalize()
{
    const int c = threadIdx.x;
    float s = 0.f, s2 = 0.f;
    #pragma unroll 8
    for (int rb = 0; rb < 256; rb++) {
        s  += g_psum [rb*COUT + c];
        s2 += g_psum2[rb*COUT + c];
    }
    const float inv = 1.0f / 65536.0f;
    float mean = s * inv;
    float var  = __fmaf_rn(-mean, mean, s2 * inv);
    g_mean[c] = mean;
    g_rstd[c] = __fdiv_rn(1.0f, __fsqrt_rn(__fadd_rn(var, 1e-5f)));
}

// ---------------- K4: kNN (unchanged, passing numerics) ----------------
#define K4_SMEM (4*N_*4 + 8*512*8)
__global__ __launch_bounds__(256, 1) void k4_knn(
    const float* __restrict__ p1, const float* __restrict__ out)
{
    extern __shared__ char smraw[];
    float* sx  = (float*)smraw;
    float* sy  = sx + N_;
    float* sz  = sy + N_;
    float* srr = sz + N_;
    ull*  cand = (ull*)(srr + N_);

    const int b   = blockIdx.x >> 4;
    const int blk = blockIdx.x & 15;
    const float* pb = p1 + (size_t)b * N_ * 3;

    for (int i = threadIdx.x; i < N_; i += 256) {
        float a = pb[3*i], bb = pb[3*i+1], c = pb[3*i+2];
        sx[i]=a; sy[i]=bb; sz[i]=c;
        srr[i] = __fmaf_rn(c, c, __fmaf_rn(a, a, __fmul_rn(bb, bb)));
    }
    __syncthreads();

    const int w = threadIdx.x >> 5, lane = threadIdx.x & 31;
    const float* p2base = out + (size_t)B_*M_*COUT;

    for (int qi = 0; qi < 16; qi++) {
        const int m = blk*128 + qi*8 + w;
        const float* q = p2base + ((size_t)b*M_ + m)*3;
        const float qx = q[0], qy = q[1], qz = q[2];
        const float qq = __fmaf_rn(qz, qz, __fmaf_rn(qx, qx, __fmul_rn(qy, qy)));

        float kd[16]; int ki[16];
        #pragma unroll
        for (int j = 0; j < 16; j++) { kd[j] = 3.4e38f; ki[j] = 0x7fffffff; }

        for (int i = lane; i < N_; i += 32) {
            float dot = __fmaf_rn(qz, sz[i], __fmaf_rn(qy, sy[i], __fmul_rn(qx, sx[i])));
            float d2  = __fmaf_rn(-2.0f, dot, __fadd_rn(qq, srr[i]));
            if (d2 < kd[15]) {
                float cd = d2; int ci = i;
                #pragma unroll
                for (int j = 0; j < 16; j++) {
                    if (cd < kd[j]) {
                        float td = kd[j]; int ti = ki[j];
                        kd[j] = cd; ki[j] = ci; cd = td; ci = ti;
                    }
                }
            }
        }
        ull* my = cand + w*512 + lane*16;
        #pragma unroll
        for (int j = 0; j < 16; j++) {
            unsigned ub = __float_as_uint(kd[j]);
            ub = (ub & 0x80000000u) ? ~ub : (ub | 0x80000000u);
            my[j] = ((ull)ub << 32) | (unsigned)ki[j];
        }
        __syncwarp();

        int ptr = 0;
        int* nbrq = g_nbr + ((size_t)b*M_ + m) * KNN_K;
        for (int r = 0; r < KNN_K; r++) {
            ull mykey = cand[w*512 + lane*16 + ptr];
            ull best = mykey; int bl = lane;
            #pragma unroll
            for (int o = 16; o > 0; o >>= 1) {
                ull ok = __shfl_down_sync(0xffffffffu, best, o);
                int ol = __shfl_down_sync(0xffffffffu, bl, o);
                if (ok < best) { best = ok; bl = ol; }
            }
            best = __shfl_sync(0xffffffffu, best, 0);
            bl   = __shfl_sync(0xffffffffu, bl, 0);
            if (lane == bl) ptr++;
            if (lane == 0) nbrq[r] = (int)(best & 0xffffffffu);
        }
        __syncwarp();
    }
}

// ---------------- K5: gather + max-pool + BN + ReLU (unchanged) ----------------
__global__ __launch_bounds__(256) void k5_out(
    const float* __restrict__ gamma, const float* __restrict__ beta,
    float* __restrict__ out)
{
    __shared__ int snbr[KNN_K];
    const int bid = blockIdx.x;
    const int b = bid >> 11, m = bid & 2047;
    const int c = threadIdx.x;
    if (c < KNN_K) snbr[c] = g_nbr[((size_t)b*M_ + m)*KNN_K + c];
    __syncthreads();

    float mx = -3.4e38f, mn = 3.4e38f;
    #pragma unroll
    for (int i = 0; i < KNN_K; i++) {
        float v = g_h[((size_t)b*N_ + snbr[i])*COUT + c];
        mx = fmaxf(mx, v); mn = fminf(mn, v);
    }
    float g = gamma[c];
    float h = (g >= 0.0f) ? mx : mn;
    float t = __fmul_rn(__fmul_rn(__fadd_rn(h, -g_mean[c]), g_rstd[c]), g);
    t = __fadd_rn(t, beta[c]);
    out[((size_t)b*M_ + m)*COUT + c] = fmaxf(t, 0.0f);
}

// ---------------- launch ----------------
extern "C" void kernel_launch(void* const* d_in, const int* in_sizes, int n_in,
                              void* d_out, int out_size)
{
    (void)in_sizes; (void)n_in; (void)out_size;
    const float* x     = (const float*)d_in[0];
    const float* p1    = (const float*)d_in[1];
    const float* W     = (const float*)d_in[2];
    const float* gamma = (const float*)d_in[3];
    const float* beta  = (const float*)d_in[4];
    float* out = (float*)d_out;

    cudaFuncSetAttribute(k1_fps_mm, cudaFuncAttributeMaxDynamicSharedMemorySize, SMEM_K1);
    cudaFuncSetAttribute(k4_knn,    cudaFuncAttributeMaxDynamicSharedMemorySize, K4_SMEM);

    k1_fps_mm<<<B_ + (B_*N_/128)*(COUT/128), 1024, SMEM_K1>>>(x, p1, W, out);
    k2_stats<<<256, 256>>>();
    k3_finalize<<<1, 256>>>();
    k4_knn<<<B_ * 16, 256, K4_SMEM>>>(p1, out);
    k5_out<<<B_ * M_, 256>>>(gamma, beta, out);
}